// round 13
// baseline (speedup 1.0000x reference)
#include <cuda_runtime.h>
#include <cuda_bf16.h>
#include <cstddef>

// Problem constants
#define BB   64
#define NN   197
#define CC   768
#define HH   12
#define HD   64
#define MQ   (BB*NN)        // 12608 rows
#define QKVN (3*CC)         // 2304

// ---------------- scratch (device globals; no allocation allowed) ----------
__device__ float g_qkv[(size_t)MQ * QKVN];     // [B*N, 3C]
__device__ float g_ao [(size_t)MQ * CC];       // attention output [B,N,C]
__device__ float g_gs [(size_t)BB * HH * (NN-1)]; // per-head CLS row probs

// ---------------- SGEMM: C[m,n] = sum_k A[m,k]*W[n,k] (+bias[n]) ------------
// A: [M,K] row-major, W: [Nn,K] row-major. BM=BN=128, BK=8, 256 threads, 8x8/thr.
__global__ __launch_bounds__(256)
void sgemm_nt(const float* __restrict__ A, const float* __restrict__ W,
              const float* __restrict__ bias, float* __restrict__ C,
              int M, int Nn, int K)
{
    __shared__ float As[8][128];
    __shared__ float Bs[8][128];

    const int tid = threadIdx.x;
    const int bm  = blockIdx.y, bn = blockIdx.x;

    const int lr = tid >> 1;            // 0..127  row within tile
    const int lk = (tid & 1) * 4;       // 0 or 4  k offset

    const int tx = tid & 15;            // n-slot
    const int ty = tid >> 4;            // m-slot

    float acc[8][8];
#pragma unroll
    for (int i = 0; i < 8; i++)
#pragma unroll
        for (int j = 0; j < 8; j++) acc[i][j] = 0.f;

    const int  arow = bm*128 + lr;
    const bool aval = (arow < M);
    const float* Ap = A + (size_t)arow * K + lk;
    const float* Wp = W + (size_t)(bn*128 + lr) * K + lk;

    for (int k0 = 0; k0 < K; k0 += 8) {
        float4 av = aval ? *(const float4*)Ap : make_float4(0.f,0.f,0.f,0.f);
        float4 bv = *(const float4*)Wp;
        As[lk+0][lr] = av.x; As[lk+1][lr] = av.y; As[lk+2][lr] = av.z; As[lk+3][lr] = av.w;
        Bs[lk+0][lr] = bv.x; Bs[lk+1][lr] = bv.y; Bs[lk+2][lr] = bv.z; Bs[lk+3][lr] = bv.w;
        __syncthreads();

#pragma unroll
        for (int k = 0; k < 8; k++) {
            float4 A0 = *(const float4*)&As[k][ty*4];
            float4 A1 = *(const float4*)&As[k][64 + ty*4];
            float4 B0 = *(const float4*)&Bs[k][tx*4];
            float4 B1 = *(const float4*)&Bs[k][64 + tx*4];
            float a[8] = {A0.x,A0.y,A0.z,A0.w, A1.x,A1.y,A1.z,A1.w};
            float b[8] = {B0.x,B0.y,B0.z,B0.w, B1.x,B1.y,B1.z,B1.w};
#pragma unroll
            for (int i = 0; i < 8; i++)
#pragma unroll
                for (int j = 0; j < 8; j++)
                    acc[i][j] = fmaf(a[i], b[j], acc[i][j]);
        }
        __syncthreads();
        Ap += 8; Wp += 8;
    }

    const int c0 = bn*128 + tx*4;
    const int c1 = c0 + 64;
    float4 bias0 = make_float4(0.f,0.f,0.f,0.f), bias1 = bias0;
    if (bias) {
        bias0 = *(const float4*)(bias + c0);
        bias1 = *(const float4*)(bias + c1);
    }
#pragma unroll
    for (int i = 0; i < 8; i++) {
        int m = bm*128 + ((i < 4) ? (ty*4 + i) : (64 + ty*4 + (i-4)));
        if (m >= M) continue;
        float* crow = C + (size_t)m * Nn;
        float4 v0 = make_float4(acc[i][0]+bias0.x, acc[i][1]+bias0.y,
                                acc[i][2]+bias0.z, acc[i][3]+bias0.w);
        float4 v1 = make_float4(acc[i][4]+bias1.x, acc[i][5]+bias1.y,
                                acc[i][6]+bias1.z, acc[i][7]+bias1.w);
        *(float4*)(crow + c0) = v0;
        *(float4*)(crow + c1) = v1;
    }
}

// ---------------- Attention: one CTA per (b,h) -----------------------------
// SMEM: K [197][68], V [197][64], Qchunk [32][68], S [32][200]  (~138 KB)
#define LDK 68
#define LDV 64
#define LDQ 68
#define LDS 200
#define ATTN_SMEM ((NN*LDK + NN*LDV + 32*LDQ + 32*LDS) * (int)sizeof(float))

__global__ __launch_bounds__(256)
void attn_kernel(const float* __restrict__ qkv, float* __restrict__ ao,
                 float* __restrict__ gs)
{
    extern __shared__ float sm[];
    float* Ks = sm;                    // 197*68
    float* Vs = Ks + NN*LDK;           // 197*64
    float* Qs = Vs + NN*LDV;           // 32*68
    float* Ss = Qs + 32*LDQ;           // 32*200

    const int tid = threadIdx.x;
    const int bh  = blockIdx.x;
    const int b   = bh / HH;
    const int h   = bh % HH;
    const float scale = 0.125f;        // 64^-0.5

    // ---- load K, V tiles for this (b,h) ----
    for (int idx = tid; idx < NN*16; idx += 256) {
        int m  = idx >> 4;
        int e4 = idx & 15;
        const float* base = qkv + (size_t)(b*NN + m) * QKVN + h*HD + e4*4;
        float4 kk = *(const float4*)(base + CC);
        float4 vv = *(const float4*)(base + 2*CC);
        *(float4*)&Ks[m*LDK + e4*4] = kk;
        *(float4*)&Vs[m*LDV + e4*4] = vv;
    }
    __syncthreads();

    for (int c = 0; c < 7; c++) {        // ceil(197/32) chunks of queries
        const int i0 = c * 32;

        // ---- load Q chunk (zero-pad past 197) ----
        for (int idx = tid; idx < 32*16; idx += 256) {
            int r  = idx >> 4;
            int e4 = idx & 15;
            int gr = i0 + r;
            float4 v = make_float4(0.f,0.f,0.f,0.f);
            if (gr < NN)
                v = *(const float4*)(qkv + (size_t)(b*NN + gr)*QKVN + h*HD + e4*4);
            *(float4*)&Qs[r*LDQ + e4*4] = v;
        }
        __syncthreads();

        // ---- S = scale * Q K^T : thread = (is 0..7) x (jl 0..31); 4i x 7j tile
        {
            const int jl = tid & 31;
            const int is = tid >> 5;
            float acc[4][7];
#pragma unroll
            for (int r = 0; r < 4; r++)
#pragma unroll
                for (int jj = 0; jj < 7; jj++) acc[r][jj] = 0.f;

#pragma unroll 4
            for (int k = 0; k < HD; k += 4) {
                float4 qv[4];
#pragma unroll
                for (int r = 0; r < 4; r++)
                    qv[r] = *(const float4*)&Qs[(is + 8*r)*LDQ + k];
#pragma unroll
                for (int jj = 0; jj < 7; jj++) {
                    int j = jl + 32*jj;             // may exceed 196; reads stay in smem
                    float4 kv = *(const float4*)&Ks[j*LDK + k];
#pragma unroll
                    for (int r = 0; r < 4; r++) {
                        acc[r][jj] = fmaf(qv[r].x, kv.x, acc[r][jj]);
                        acc[r][jj] = fmaf(qv[r].y, kv.y, acc[r][jj]);
                        acc[r][jj] = fmaf(qv[r].z, kv.z, acc[r][jj]);
                        acc[r][jj] = fmaf(qv[r].w, kv.w, acc[r][jj]);
                    }
                }
            }
#pragma unroll
            for (int jj = 0; jj < 7; jj++) {
                int j = jl + 32*jj;
                if (j < NN)
#pragma unroll
                    for (int r = 0; r < 4; r++)
                        Ss[(is + 8*r)*LDS + j] = acc[r][jj] * scale;
            }
        }
        __syncthreads();

        // ---- softmax per row: 8 threads / row ----
        {
            const int t = tid & 7;
            const int i = tid >> 3;      // 0..31
            float* row = &Ss[i*LDS];
            float mx = -1e30f;
            for (int j = t; j < NN; j += 8) mx = fmaxf(mx, row[j]);
            mx = fmaxf(mx, __shfl_xor_sync(0xffffffffu, mx, 4));
            mx = fmaxf(mx, __shfl_xor_sync(0xffffffffu, mx, 2));
            mx = fmaxf(mx, __shfl_xor_sync(0xffffffffu, mx, 1));
            float sum = 0.f;
            for (int j = t; j < NN; j += 8) {
                float e = __expf(row[j] - mx);
                row[j] = e;
                sum += e;
            }
            sum += __shfl_xor_sync(0xffffffffu, sum, 4);
            sum += __shfl_xor_sync(0xffffffffu, sum, 2);
            sum += __shfl_xor_sync(0xffffffffu, sum, 1);
            float inv = 1.f / sum;
            for (int j = t; j < NN; j += 8) row[j] *= inv;
        }
        __syncthreads();

        // ---- CLS-row probs (row 0 of the whole matrix) ----
        if (c == 0) {
            for (int p = tid; p < NN-1; p += 256)
                gs[(size_t)bh * (NN-1) + p] = Ss[p + 1];
        }

        // ---- O = P V : thread = (is2 0..15) x (eg 0..15); rows {is2, is2+16}
        {
            const int eg  = tid & 15;
            const int is2 = tid >> 4;
            float4 o0 = make_float4(0.f,0.f,0.f,0.f);
            float4 o1 = make_float4(0.f,0.f,0.f,0.f);
            const float* p0r = &Ss[is2*LDS];
            const float* p1r = &Ss[(is2+16)*LDS];
#pragma unroll 4
            for (int j = 0; j < NN; j++) {
                float p0 = p0r[j];
                float p1 = p1r[j];
                float4 vv = *(const float4*)&Vs[j*LDV + eg*4];
                o0.x = fmaf(p0, vv.x, o0.x); o0.y = fmaf(p0, vv.y, o0.y);
                o0.z = fmaf(p0, vv.z, o0.z); o0.w = fmaf(p0, vv.w, o0.w);
                o1.x = fmaf(p1, vv.x, o1.x); o1.y = fmaf(p1, vv.y, o1.y);
                o1.z = fmaf(p1, vv.z, o1.z); o1.w = fmaf(p1, vv.w, o1.w);
            }
            int g0 = i0 + is2, g1 = i0 + is2 + 16;
            if (g0 < NN)
                *(float4*)(ao + (size_t)(b*NN + g0)*CC + h*HD + eg*4) = o0;
            if (g1 < NN)
                *(float4*)(ao + (size_t)(b*NN + g1)*CC + h*HD + eg*4) = o1;
        }
        __syncthreads();
    }
}

// ---------------- global_attn = mean over heads ------------------------------
__global__ __launch_bounds__(256)
void gattn_reduce(const float* __restrict__ gs, float* __restrict__ outg)
{
    int idx = blockIdx.x * 256 + threadIdx.x;
    if (idx >= BB*(NN-1)) return;
    int b = idx / (NN-1), p = idx % (NN-1);
    float s = 0.f;
#pragma unroll
    for (int h = 0; h < HH; h++)
        s += gs[(size_t)(b*HH + h)*(NN-1) + p];
    outg[idx] = s * (1.0f / HH);
}

// ---------------- launch ------------------------------------------------------
extern "C" void kernel_launch(void* const* d_in, const int* in_sizes, int n_in,
                              void* d_out, int out_size)
{
    const float* x      = (const float*)d_in[0];   // [64,197,768]
    const float* w_qkv  = (const float*)d_in[1];   // [2304,768]
    const float* w_proj = (const float*)d_in[2];   // [768,768]
    const float* b_proj = (const float*)d_in[3];   // [768]
    float* out = (float*)d_out;                    // [out | global_attn]

    float *qkv_p, *ao_p, *gs_p;
    cudaGetSymbolAddress((void**)&qkv_p, g_qkv);
    cudaGetSymbolAddress((void**)&ao_p,  g_ao);
    cudaGetSymbolAddress((void**)&gs_p,  g_gs);

    cudaFuncSetAttribute(attn_kernel,
                         cudaFuncAttributeMaxDynamicSharedMemorySize, ATTN_SMEM);

    // 1) QKV GEMM: [12608,768] x [2304,768]^T -> g_qkv
    {
        dim3 grid(QKVN/128, (MQ + 127)/128);
        sgemm_nt<<<grid, 256>>>(x, w_qkv, nullptr, qkv_p, MQ, QKVN, CC);
    }
    // 2) attention per (b,h)
    attn_kernel<<<BB*HH, 256, ATTN_SMEM>>>(qkv_p, ao_p, gs_p);

    // 3) proj GEMM + bias -> d_out[0 : B*N*C]
    {
        dim3 grid(CC/128, (MQ + 127)/128);
        sgemm_nt<<<grid, 256>>>(ao_p, w_proj, b_proj, out, MQ, CC, CC);
    }
    // 4) global_attn -> d_out[B*N*C : ]
    {
        int tot = BB*(NN-1);
        gattn_reduce<<<(tot + 255)/256, 256>>>(gs_p, out + (size_t)MQ*CC);
    }
}

// round 14
// speedup vs baseline: 1.5925x; 1.5925x over previous
#include <cuda_runtime.h>
#include <cuda_bf16.h>
#include <cstddef>

// Problem constants
#define BB   64
#define NN   197
#define CC   768
#define HH   12
#define HD   64
#define MQ   (BB*NN)        // 12608 rows
#define QKVN (3*CC)         // 2304

// ---------------- scratch (device globals; no allocation allowed) ----------
__device__ float g_qkv[(size_t)MQ * QKVN];     // [B*N, 3C]
__device__ float g_ao [(size_t)MQ * CC];       // attention output [B,N,C]
__device__ float g_gs [(size_t)BB * HH * (NN-1)]; // per-head CLS row probs

// ---------------- SGEMM: C[m,n] = sum_k A[m,k]*W[n,k] (+bias[n]) ------------
// A: [M,K] row-major, W: [Nn,K] row-major. BM=BN=128, BK=8, 256 threads, 8x8/thr.
__global__ __launch_bounds__(256)
void sgemm_nt(const float* __restrict__ A, const float* __restrict__ W,
              const float* __restrict__ bias, float* __restrict__ C,
              int M, int Nn, int K)
{
    __shared__ float As[8][128];
    __shared__ float Bs[8][128];

    const int tid = threadIdx.x;
    const int bm  = blockIdx.y, bn = blockIdx.x;

    const int lr = tid >> 1;            // 0..127  row within tile
    const int lk = (tid & 1) * 4;       // 0 or 4  k offset

    const int tx = tid & 15;            // n-slot
    const int ty = tid >> 4;            // m-slot

    float acc[8][8];
#pragma unroll
    for (int i = 0; i < 8; i++)
#pragma unroll
        for (int j = 0; j < 8; j++) acc[i][j] = 0.f;

    const int  arow = bm*128 + lr;
    const bool aval = (arow < M);
    const float* Ap = A + (size_t)arow * K + lk;
    const float* Wp = W + (size_t)(bn*128 + lr) * K + lk;

    for (int k0 = 0; k0 < K; k0 += 8) {
        float4 av = aval ? *(const float4*)Ap : make_float4(0.f,0.f,0.f,0.f);
        float4 bv = *(const float4*)Wp;
        As[lk+0][lr] = av.x; As[lk+1][lr] = av.y; As[lk+2][lr] = av.z; As[lk+3][lr] = av.w;
        Bs[lk+0][lr] = bv.x; Bs[lk+1][lr] = bv.y; Bs[lk+2][lr] = bv.z; Bs[lk+3][lr] = bv.w;
        __syncthreads();

#pragma unroll
        for (int k = 0; k < 8; k++) {
            float4 A0 = *(const float4*)&As[k][ty*4];
            float4 A1 = *(const float4*)&As[k][64 + ty*4];
            float4 B0 = *(const float4*)&Bs[k][tx*4];
            float4 B1 = *(const float4*)&Bs[k][64 + tx*4];
            float a[8] = {A0.x,A0.y,A0.z,A0.w, A1.x,A1.y,A1.z,A1.w};
            float b[8] = {B0.x,B0.y,B0.z,B0.w, B1.x,B1.y,B1.z,B1.w};
#pragma unroll
            for (int i = 0; i < 8; i++)
#pragma unroll
                for (int j = 0; j < 8; j++)
                    acc[i][j] = fmaf(a[i], b[j], acc[i][j]);
        }
        __syncthreads();
        Ap += 8; Wp += 8;
    }

    const int c0 = bn*128 + tx*4;
    const int c1 = c0 + 64;
    float4 bias0 = make_float4(0.f,0.f,0.f,0.f), bias1 = bias0;
    if (bias) {
        bias0 = *(const float4*)(bias + c0);
        bias1 = *(const float4*)(bias + c1);
    }
#pragma unroll
    for (int i = 0; i < 8; i++) {
        int m = bm*128 + ((i < 4) ? (ty*4 + i) : (64 + ty*4 + (i-4)));
        if (m >= M) continue;
        float* crow = C + (size_t)m * Nn;
        float4 v0 = make_float4(acc[i][0]+bias0.x, acc[i][1]+bias0.y,
                                acc[i][2]+bias0.z, acc[i][3]+bias0.w);
        float4 v1 = make_float4(acc[i][4]+bias1.x, acc[i][5]+bias1.y,
                                acc[i][6]+bias1.z, acc[i][7]+bias1.w);
        *(float4*)(crow + c0) = v0;
        *(float4*)(crow + c1) = v1;
    }
}

// ---------------- Attention: one CTA per (b,h) -----------------------------
// SMEM: K [197][68], V [197][64], Qchunk [32][68], S [32][200]  (~138 KB)
#define LDK 68
#define LDV 64
#define LDQ 68
#define LDS 200
#define ATTN_SMEM ((NN*LDK + NN*LDV + 32*LDQ + 32*LDS) * (int)sizeof(float))

__global__ __launch_bounds__(256)
void attn_kernel(const float* __restrict__ qkv, float* __restrict__ ao,
                 float* __restrict__ gs)
{
    extern __shared__ float sm[];
    float* Ks = sm;                    // 197*68
    float* Vs = Ks + NN*LDK;           // 197*64
    float* Qs = Vs + NN*LDV;           // 32*68
    float* Ss = Qs + 32*LDQ;           // 32*200

    const int tid = threadIdx.x;
    const int bh  = blockIdx.x;
    const int b   = bh / HH;
    const int h   = bh % HH;
    const float scale = 0.125f;        // 64^-0.5

    // ---- load K, V tiles for this (b,h) ----
    for (int idx = tid; idx < NN*16; idx += 256) {
        int m  = idx >> 4;
        int e4 = idx & 15;
        const float* base = qkv + (size_t)(b*NN + m) * QKVN + h*HD + e4*4;
        float4 kk = *(const float4*)(base + CC);
        float4 vv = *(const float4*)(base + 2*CC);
        *(float4*)&Ks[m*LDK + e4*4] = kk;
        *(float4*)&Vs[m*LDV + e4*4] = vv;
    }
    __syncthreads();

    for (int c = 0; c < 7; c++) {        // ceil(197/32) chunks of queries
        const int i0 = c * 32;

        // ---- load Q chunk (zero-pad past 197) ----
        for (int idx = tid; idx < 32*16; idx += 256) {
            int r  = idx >> 4;
            int e4 = idx & 15;
            int gr = i0 + r;
            float4 v = make_float4(0.f,0.f,0.f,0.f);
            if (gr < NN)
                v = *(const float4*)(qkv + (size_t)(b*NN + gr)*QKVN + h*HD + e4*4);
            *(float4*)&Qs[r*LDQ + e4*4] = v;
        }
        __syncthreads();

        // ---- S = scale * Q K^T : thread = (is 0..7) x (jl 0..31); 4i x 7j tile
        {
            const int jl = tid & 31;
            const int is = tid >> 5;
            float acc[4][7];
#pragma unroll
            for (int r = 0; r < 4; r++)
#pragma unroll
                for (int jj = 0; jj < 7; jj++) acc[r][jj] = 0.f;

#pragma unroll 4
            for (int k = 0; k < HD; k += 4) {
                float4 qv[4];
#pragma unroll
                for (int r = 0; r < 4; r++)
                    qv[r] = *(const float4*)&Qs[(is + 8*r)*LDQ + k];
#pragma unroll
                for (int jj = 0; jj < 7; jj++) {
                    int j = jl + 32*jj;             // may exceed 196; reads stay in smem
                    float4 kv = *(const float4*)&Ks[j*LDK + k];
#pragma unroll
                    for (int r = 0; r < 4; r++) {
                        acc[r][jj] = fmaf(qv[r].x, kv.x, acc[r][jj]);
                        acc[r][jj] = fmaf(qv[r].y, kv.y, acc[r][jj]);
                        acc[r][jj] = fmaf(qv[r].z, kv.z, acc[r][jj]);
                        acc[r][jj] = fmaf(qv[r].w, kv.w, acc[r][jj]);
                    }
                }
            }
#pragma unroll
            for (int jj = 0; jj < 7; jj++) {
                int j = jl + 32*jj;
                if (j < NN)
#pragma unroll
                    for (int r = 0; r < 4; r++)
                        Ss[(is + 8*r)*LDS + j] = acc[r][jj] * scale;
            }
        }
        __syncthreads();

        // ---- softmax per row: 8 threads / row ----
        {
            const int t = tid & 7;
            const int i = tid >> 3;      // 0..31
            float* row = &Ss[i*LDS];
            float mx = -1e30f;
            for (int j = t; j < NN; j += 8) mx = fmaxf(mx, row[j]);
            mx = fmaxf(mx, __shfl_xor_sync(0xffffffffu, mx, 4));
            mx = fmaxf(mx, __shfl_xor_sync(0xffffffffu, mx, 2));
            mx = fmaxf(mx, __shfl_xor_sync(0xffffffffu, mx, 1));
            float sum = 0.f;
            for (int j = t; j < NN; j += 8) {
                float e = __expf(row[j] - mx);
                row[j] = e;
                sum += e;
            }
            sum += __shfl_xor_sync(0xffffffffu, sum, 4);
            sum += __shfl_xor_sync(0xffffffffu, sum, 2);
            sum += __shfl_xor_sync(0xffffffffu, sum, 1);
            float inv = 1.f / sum;
            for (int j = t; j < NN; j += 8) row[j] *= inv;
        }
        __syncthreads();

        // ---- CLS-row probs (row 0 of the whole matrix) ----
        if (c == 0) {
            for (int p = tid; p < NN-1; p += 256)
                gs[(size_t)bh * (NN-1) + p] = Ss[p + 1];
        }

        // ---- O = P V : thread = (is2 0..15) x (eg 0..15); rows {is2, is2+16}
        {
            const int eg  = tid & 15;
            const int is2 = tid >> 4;
            float4 o0 = make_float4(0.f,0.f,0.f,0.f);
            float4 o1 = make_float4(0.f,0.f,0.f,0.f);
            const float* p0r = &Ss[is2*LDS];
            const float* p1r = &Ss[(is2+16)*LDS];
#pragma unroll 4
            for (int j = 0; j < NN; j++) {
                float p0 = p0r[j];
                float p1 = p1r[j];
                float4 vv = *(const float4*)&Vs[j*LDV + eg*4];
                o0.x = fmaf(p0, vv.x, o0.x); o0.y = fmaf(p0, vv.y, o0.y);
                o0.z = fmaf(p0, vv.z, o0.z); o0.w = fmaf(p0, vv.w, o0.w);
                o1.x = fmaf(p1, vv.x, o1.x); o1.y = fmaf(p1, vv.y, o1.y);
                o1.z = fmaf(p1, vv.z, o1.z); o1.w = fmaf(p1, vv.w, o1.w);
            }
            int g0 = i0 + is2, g1 = i0 + is2 + 16;
            if (g0 < NN)
                *(float4*)(ao + (size_t)(b*NN + g0)*CC + h*HD + eg*4) = o0;
            if (g1 < NN)
                *(float4*)(ao + (size_t)(b*NN + g1)*CC + h*HD + eg*4) = o1;
        }
        __syncthreads();
    }
}

// ---------------- global_attn = mean over heads ------------------------------
__global__ __launch_bounds__(256)
void gattn_reduce(const float* __restrict__ gs, float* __restrict__ outg)
{
    int idx = blockIdx.x * 256 + threadIdx.x;
    if (idx >= BB*(NN-1)) return;
    int b = idx / (NN-1), p = idx % (NN-1);
    float s = 0.f;
#pragma unroll
    for (int h = 0; h < HH; h++)
        s += gs[(size_t)(b*HH + h)*(NN-1) + p];
    outg[idx] = s * (1.0f / HH);
}

// ---------------- launch ------------------------------------------------------
extern "C" void kernel_launch(void* const* d_in, const int* in_sizes, int n_in,
                              void* d_out, int out_size)
{
    const float* x      = (const float*)d_in[0];   // [64,197,768]
    const float* w_qkv  = (const float*)d_in[1];   // [2304,768]
    const float* w_proj = (const float*)d_in[2];   // [768,768]
    const float* b_proj = (const float*)d_in[3];   // [768]
    float* out = (float*)d_out;                    // [out | global_attn]

    float *qkv_p, *ao_p, *gs_p;
    cudaGetSymbolAddress((void**)&qkv_p, g_qkv);
    cudaGetSymbolAddress((void**)&ao_p,  g_ao);
    cudaGetSymbolAddress((void**)&gs_p,  g_gs);

    cudaFuncSetAttribute(attn_kernel,
                         cudaFuncAttributeMaxDynamicSharedMemorySize, ATTN_SMEM);

    // 1) QKV GEMM: [12608,768] x [2304,768]^T -> g_qkv
    {
        dim3 grid(QKVN/128, (MQ + 127)/128);
        sgemm_nt<<<grid, 256>>>(x, w_qkv, nullptr, qkv_p, MQ, QKVN, CC);
    }
    // 2) attention per (b,h)
    attn_kernel<<<BB*HH, 256, ATTN_SMEM>>>(qkv_p, ao_p, gs_p);

    // 3) proj GEMM + bias -> d_out[0 : B*N*C]
    {
        dim3 grid(CC/128, (MQ + 127)/128);
        sgemm_nt<<<grid, 256>>>(ao_p, w_proj, b_proj, out, MQ, CC, CC);
    }
    // 4) global_attn -> d_out[B*N*C : ]
    {
        int tot = BB*(NN-1);
        gattn_reduce<<<(tot + 255)/256, 256>>>(gs_p, out + (size_t)MQ*CC);
    }
}

// round 15
// speedup vs baseline: 1.5932x; 1.0004x over previous
#include <cuda_runtime.h>
#include <cuda_bf16.h>
#include <cstddef>

// Problem constants
#define BB   64
#define NN   197
#define CC   768
#define HH   12
#define HD   64
#define MQ   (BB*NN)        // 12608 rows
#define QKVN (3*CC)         // 2304

// ---------------- scratch (device globals; no allocation allowed) ----------
__device__ float g_qkv[(size_t)MQ * QKVN];     // [B*N, 3C]
__device__ float g_ao [(size_t)MQ * CC];       // attention output [B,N,C]
__device__ float g_gs [(size_t)BB * HH * (NN-1)]; // per-head CLS row probs

// ---------------- SGEMM: C[m,n] = sum_k A[m,k]*W[n,k] (+bias[n]) ------------
// A: [M,K] row-major, W: [Nn,K] row-major. BM=BN=128, BK=8, 256 threads, 8x8/thr.
__global__ __launch_bounds__(256)
void sgemm_nt(const float* __restrict__ A, const float* __restrict__ W,
              const float* __restrict__ bias, float* __restrict__ C,
              int M, int Nn, int K)
{
    __shared__ float As[8][128];
    __shared__ float Bs[8][128];

    const int tid = threadIdx.x;
    const int bm  = blockIdx.y, bn = blockIdx.x;

    const int lr = tid >> 1;            // 0..127  row within tile
    const int lk = (tid & 1) * 4;       // 0 or 4  k offset

    const int tx = tid & 15;            // n-slot
    const int ty = tid >> 4;            // m-slot

    float acc[8][8];
#pragma unroll
    for (int i = 0; i < 8; i++)
#pragma unroll
        for (int j = 0; j < 8; j++) acc[i][j] = 0.f;

    const int  arow = bm*128 + lr;
    const bool aval = (arow < M);
    const float* Ap = A + (size_t)arow * K + lk;
    const float* Wp = W + (size_t)(bn*128 + lr) * K + lk;

    for (int k0 = 0; k0 < K; k0 += 8) {
        float4 av = aval ? *(const float4*)Ap : make_float4(0.f,0.f,0.f,0.f);
        float4 bv = *(const float4*)Wp;
        As[lk+0][lr] = av.x; As[lk+1][lr] = av.y; As[lk+2][lr] = av.z; As[lk+3][lr] = av.w;
        Bs[lk+0][lr] = bv.x; Bs[lk+1][lr] = bv.y; Bs[lk+2][lr] = bv.z; Bs[lk+3][lr] = bv.w;
        __syncthreads();

#pragma unroll
        for (int k = 0; k < 8; k++) {
            float4 A0 = *(const float4*)&As[k][ty*4];
            float4 A1 = *(const float4*)&As[k][64 + ty*4];
            float4 B0 = *(const float4*)&Bs[k][tx*4];
            float4 B1 = *(const float4*)&Bs[k][64 + tx*4];
            float a[8] = {A0.x,A0.y,A0.z,A0.w, A1.x,A1.y,A1.z,A1.w};
            float b[8] = {B0.x,B0.y,B0.z,B0.w, B1.x,B1.y,B1.z,B1.w};
#pragma unroll
            for (int i = 0; i < 8; i++)
#pragma unroll
                for (int j = 0; j < 8; j++)
                    acc[i][j] = fmaf(a[i], b[j], acc[i][j]);
        }
        __syncthreads();
        Ap += 8; Wp += 8;
    }

    const int c0 = bn*128 + tx*4;
    const int c1 = c0 + 64;
    float4 bias0 = make_float4(0.f,0.f,0.f,0.f), bias1 = bias0;
    if (bias) {
        bias0 = *(const float4*)(bias + c0);
        bias1 = *(const float4*)(bias + c1);
    }
#pragma unroll
    for (int i = 0; i < 8; i++) {
        int m = bm*128 + ((i < 4) ? (ty*4 + i) : (64 + ty*4 + (i-4)));
        if (m >= M) continue;
        float* crow = C + (size_t)m * Nn;
        float4 v0 = make_float4(acc[i][0]+bias0.x, acc[i][1]+bias0.y,
                                acc[i][2]+bias0.z, acc[i][3]+bias0.w);
        float4 v1 = make_float4(acc[i][4]+bias1.x, acc[i][5]+bias1.y,
                                acc[i][6]+bias1.z, acc[i][7]+bias1.w);
        *(float4*)(crow + c0) = v0;
        *(float4*)(crow + c1) = v1;
    }
}

// ---------------- Attention: one CTA per (b,h) -----------------------------
// SMEM: K [197][68], V [197][64], Qchunk [32][68], S [32][200]  (~138 KB)
#define LDK 68
#define LDV 64
#define LDQ 68
#define LDS 200
#define ATTN_SMEM ((NN*LDK + NN*LDV + 32*LDQ + 32*LDS) * (int)sizeof(float))

__global__ __launch_bounds__(256)
void attn_kernel(const float* __restrict__ qkv, float* __restrict__ ao,
                 float* __restrict__ gs)
{
    extern __shared__ float sm[];
    float* Ks = sm;                    // 197*68
    float* Vs = Ks + NN*LDK;           // 197*64
    float* Qs = Vs + NN*LDV;           // 32*68
    float* Ss = Qs + 32*LDQ;           // 32*200

    const int tid = threadIdx.x;
    const int bh  = blockIdx.x;
    const int b   = bh / HH;
    const int h   = bh % HH;
    const float scale = 0.125f;        // 64^-0.5

    // ---- load K, V tiles for this (b,h) ----
    for (int idx = tid; idx < NN*16; idx += 256) {
        int m  = idx >> 4;
        int e4 = idx & 15;
        const float* base = qkv + (size_t)(b*NN + m) * QKVN + h*HD + e4*4;
        float4 kk = *(const float4*)(base + CC);
        float4 vv = *(const float4*)(base + 2*CC);
        *(float4*)&Ks[m*LDK + e4*4] = kk;
        *(float4*)&Vs[m*LDV + e4*4] = vv;
    }
    __syncthreads();

    for (int c = 0; c < 7; c++) {        // ceil(197/32) chunks of queries
        const int i0 = c * 32;

        // ---- load Q chunk (zero-pad past 197) ----
        for (int idx = tid; idx < 32*16; idx += 256) {
            int r  = idx >> 4;
            int e4 = idx & 15;
            int gr = i0 + r;
            float4 v = make_float4(0.f,0.f,0.f,0.f);
            if (gr < NN)
                v = *(const float4*)(qkv + (size_t)(b*NN + gr)*QKVN + h*HD + e4*4);
            *(float4*)&Qs[r*LDQ + e4*4] = v;
        }
        __syncthreads();

        // ---- S = scale * Q K^T : thread = (is 0..7) x (jl 0..31); 4i x 7j tile
        {
            const int jl = tid & 31;
            const int is = tid >> 5;
            float acc[4][7];
#pragma unroll
            for (int r = 0; r < 4; r++)
#pragma unroll
                for (int jj = 0; jj < 7; jj++) acc[r][jj] = 0.f;

#pragma unroll 4
            for (int k = 0; k < HD; k += 4) {
                float4 qv[4];
#pragma unroll
                for (int r = 0; r < 4; r++)
                    qv[r] = *(const float4*)&Qs[(is + 8*r)*LDQ + k];
#pragma unroll
                for (int jj = 0; jj < 7; jj++) {
                    int j = jl + 32*jj;             // may exceed 196; reads stay in smem
                    float4 kv = *(const float4*)&Ks[j*LDK + k];
#pragma unroll
                    for (int r = 0; r < 4; r++) {
                        acc[r][jj] = fmaf(qv[r].x, kv.x, acc[r][jj]);
                        acc[r][jj] = fmaf(qv[r].y, kv.y, acc[r][jj]);
                        acc[r][jj] = fmaf(qv[r].z, kv.z, acc[r][jj]);
                        acc[r][jj] = fmaf(qv[r].w, kv.w, acc[r][jj]);
                    }
                }
            }
#pragma unroll
            for (int jj = 0; jj < 7; jj++) {
                int j = jl + 32*jj;
                if (j < NN)
#pragma unroll
                    for (int r = 0; r < 4; r++)
                        Ss[(is + 8*r)*LDS + j] = acc[r][jj] * scale;
            }
        }
        __syncthreads();

        // ---- softmax per row: 8 threads / row ----
        {
            const int t = tid & 7;
            const int i = tid >> 3;      // 0..31
            float* row = &Ss[i*LDS];
            float mx = -1e30f;
            for (int j = t; j < NN; j += 8) mx = fmaxf(mx, row[j]);
            mx = fmaxf(mx, __shfl_xor_sync(0xffffffffu, mx, 4));
            mx = fmaxf(mx, __shfl_xor_sync(0xffffffffu, mx, 2));
            mx = fmaxf(mx, __shfl_xor_sync(0xffffffffu, mx, 1));
            float sum = 0.f;
            for (int j = t; j < NN; j += 8) {
                float e = __expf(row[j] - mx);
                row[j] = e;
                sum += e;
            }
            sum += __shfl_xor_sync(0xffffffffu, sum, 4);
            sum += __shfl_xor_sync(0xffffffffu, sum, 2);
            sum += __shfl_xor_sync(0xffffffffu, sum, 1);
            float inv = 1.f / sum;
            for (int j = t; j < NN; j += 8) row[j] *= inv;
        }
        __syncthreads();

        // ---- CLS-row probs (row 0 of the whole matrix) ----
        if (c == 0) {
            for (int p = tid; p < NN-1; p += 256)
                gs[(size_t)bh * (NN-1) + p] = Ss[p + 1];
        }

        // ---- O = P V : thread = (is2 0..15) x (eg 0..15); rows {is2, is2+16}
        {
            const int eg  = tid & 15;
            const int is2 = tid >> 4;
            float4 o0 = make_float4(0.f,0.f,0.f,0.f);
            float4 o1 = make_float4(0.f,0.f,0.f,0.f);
            const float* p0r = &Ss[is2*LDS];
            const float* p1r = &Ss[(is2+16)*LDS];
#pragma unroll 4
            for (int j = 0; j < NN; j++) {
                float p0 = p0r[j];
                float p1 = p1r[j];
                float4 vv = *(const float4*)&Vs[j*LDV + eg*4];
                o0.x = fmaf(p0, vv.x, o0.x); o0.y = fmaf(p0, vv.y, o0.y);
                o0.z = fmaf(p0, vv.z, o0.z); o0.w = fmaf(p0, vv.w, o0.w);
                o1.x = fmaf(p1, vv.x, o1.x); o1.y = fmaf(p1, vv.y, o1.y);
                o1.z = fmaf(p1, vv.z, o1.z); o1.w = fmaf(p1, vv.w, o1.w);
            }
            int g0 = i0 + is2, g1 = i0 + is2 + 16;
            if (g0 < NN)
                *(float4*)(ao + (size_t)(b*NN + g0)*CC + h*HD + eg*4) = o0;
            if (g1 < NN)
                *(float4*)(ao + (size_t)(b*NN + g1)*CC + h*HD + eg*4) = o1;
        }
        __syncthreads();
    }
}

// ---------------- global_attn = mean over heads ------------------------------
__global__ __launch_bounds__(256)
void gattn_reduce(const float* __restrict__ gs, float* __restrict__ outg)
{
    int idx = blockIdx.x * 256 + threadIdx.x;
    if (idx >= BB*(NN-1)) return;
    int b = idx / (NN-1), p = idx % (NN-1);
    float s = 0.f;
#pragma unroll
    for (int h = 0; h < HH; h++)
        s += gs[(size_t)(b*HH + h)*(NN-1) + p];
    outg[idx] = s * (1.0f / HH);
}

// ---------------- launch ------------------------------------------------------
extern "C" void kernel_launch(void* const* d_in, const int* in_sizes, int n_in,
                              void* d_out, int out_size)
{
    const float* x      = (const float*)d_in[0];   // [64,197,768]
    const float* w_qkv  = (const float*)d_in[1];   // [2304,768]
    const float* w_proj = (const float*)d_in[2];   // [768,768]
    const float* b_proj = (const float*)d_in[3];   // [768]
    float* out = (float*)d_out;                    // [out | global_attn]

    float *qkv_p, *ao_p, *gs_p;
    cudaGetSymbolAddress((void**)&qkv_p, g_qkv);
    cudaGetSymbolAddress((void**)&ao_p,  g_ao);
    cudaGetSymbolAddress((void**)&gs_p,  g_gs);

    cudaFuncSetAttribute(attn_kernel,
                         cudaFuncAttributeMaxDynamicSharedMemorySize, ATTN_SMEM);

    // 1) QKV GEMM: [12608,768] x [2304,768]^T -> g_qkv
    {
        dim3 grid(QKVN/128, (MQ + 127)/128);
        sgemm_nt<<<grid, 256>>>(x, w_qkv, nullptr, qkv_p, MQ, QKVN, CC);
    }
    // 2) attention per (b,h)
    attn_kernel<<<BB*HH, 256, ATTN_SMEM>>>(qkv_p, ao_p, gs_p);

    // 3) proj GEMM + bias -> d_out[0 : B*N*C]
    {
        dim3 grid(CC/128, (MQ + 127)/128);
        sgemm_nt<<<grid, 256>>>(ao_p, w_proj, b_proj, out, MQ, CC, CC);
    }
    // 4) global_attn -> d_out[B*N*C : ]
    {
        int tot = BB*(NN-1);
        gattn_reduce<<<(tot + 255)/256, 256>>>(gs_p, out + (size_t)MQ*CC);
    }
}